// round 2
// baseline (speedup 1.0000x reference)
#include <cuda_runtime.h>
#include <math.h>

#define B   8
#define LQ  1024
#define LK  1024
#define DD  512
#define H   8

// Scratch (static device globals — allocation-guard safe). ~112 MB total.
__device__ float g_xT[3][B][DD][LQ];      // transposed inputs (q,k,v): [which][b][d][l]
__device__ float g_qT[B*H][64][LQ];       // projected Q, transposed [e][l]
__device__ float g_kT[B*H][64][LK];       // projected K, transposed [e][l]
__device__ float g_v [B*H][LK][64];       // projected V, natural   [l][e]
__device__ float g_conc[B*LQ][512];       // attention output, pre-LN

// ---------------------------------------------------------------------------
// Transpose: X[b][l][d] -> g_xT[which][b][d][l], for all three inputs.
// grid (DD/32, L/32, 3*B), block (32, 8). 32x32 tiles via smem.
// ---------------------------------------------------------------------------
__global__ __launch_bounds__(256) void transpose_kernel(
    const float* __restrict__ q, const float* __restrict__ k,
    const float* __restrict__ v)
{
    __shared__ float t[32][33];
    const int zb    = blockIdx.z;
    const int which = zb >> 3;            // /B
    const int b     = zb & 7;
    const float* src = (which == 0) ? q : (which == 1) ? k : v;
    const int d0 = blockIdx.x * 32;
    const int l0 = blockIdx.y * 32;
    const int x = threadIdx.x, y = threadIdx.y;

#pragma unroll
    for (int r = 0; r < 4; ++r)
        t[y + 8 * r][x] = src[((size_t)b * LQ + l0 + y + 8 * r) * DD + d0 + x];
    __syncthreads();
#pragma unroll
    for (int r = 0; r < 4; ++r)
        g_xT[which][b][d0 + y + 8 * r][l0 + x] = t[x][y + 8 * r];
}

// ---------------------------------------------------------------------------
// Projection: out[l][e] = sum_d XT[d][l] * W[h][d][e]
// grid (L/128, H, B), 128 threads, 128x64 tile, 8x8 per thread.
// which 0: -> g_qT[bh][e][l] (transposed), 1: -> g_kT, 2: -> g_v[bh][l][e]
// ---------------------------------------------------------------------------
__global__ __launch_bounds__(128) void proj_kernel(
    const float* __restrict__ W, int which)
{
    __shared__ float sA[64][128];   // [d][l]   32 KB
    __shared__ float sW[64][64];    // [d][e]   16 KB

    const int l0  = blockIdx.x * 128;
    const int h   = blockIdx.y;
    const int b   = blockIdx.z;
    const int bh  = b * H + h;
    const int tid = threadIdx.x;
    const int ty  = tid >> 3;       // 0..15  (l groups of 8)
    const int tx  = tid & 7;        // 0..7   (e groups of 8)

    const float* Wh = W + (size_t)h * DD * 64;
    const float(*XT)[LQ] = g_xT[which][b];

    float acc[8][8];
#pragma unroll
    for (int i = 0; i < 8; ++i)
#pragma unroll
        for (int j = 0; j < 8; ++j) acc[i][j] = 0.f;

    for (int dt = 0; dt < DD / 64; ++dt) {
        __syncthreads();
        // sA: 64 rows x 128 cols = 2048 float4, 16 per thread. Coalesced, conflict-free.
#pragma unroll
        for (int r = 0; r < 16; ++r) {
            int u = tid + r * 128;
            int row = u >> 5, c4 = u & 31;
            *(float4*)&sA[row][c4 * 4] =
                *(const float4*)&XT[dt * 64 + row][l0 + c4 * 4];
        }
        // sW: 64x64 = 1024 float4, 8 per thread.
#pragma unroll
        for (int r = 0; r < 8; ++r) {
            int u = tid + r * 128;
            int row = u >> 4, c4 = u & 15;
            *(float4*)&sW[row][c4 * 4] =
                *(const float4*)&Wh[(size_t)(dt * 64 + row) * 64 + c4 * 4];
        }
        __syncthreads();
#pragma unroll
        for (int kk = 0; kk < 64; ++kk) {
            float a[8], bb[8];
            *(float4*)(a)      = *(const float4*)&sA[kk][ty * 8];
            *(float4*)(a + 4)  = *(const float4*)&sA[kk][ty * 8 + 4];
            *(float4*)(bb)     = *(const float4*)&sW[kk][tx * 8];
            *(float4*)(bb + 4) = *(const float4*)&sW[kk][tx * 8 + 4];
#pragma unroll
            for (int i = 0; i < 8; ++i)
#pragma unroll
                for (int j = 0; j < 8; ++j) acc[i][j] += a[i] * bb[j];
        }
    }

    if (which < 2) {
        float(*out)[LQ] = (which == 0 ? g_qT : g_kT)[bh];
#pragma unroll
        for (int j = 0; j < 8; ++j) {
            float4 v0 = make_float4(acc[0][j], acc[1][j], acc[2][j], acc[3][j]);
            float4 v1 = make_float4(acc[4][j], acc[5][j], acc[6][j], acc[7][j]);
            *(float4*)&out[tx * 8 + j][l0 + ty * 8]     = v0;
            *(float4*)&out[tx * 8 + j][l0 + ty * 8 + 4] = v1;
        }
    } else {
        float(*out)[64] = g_v[bh];
#pragma unroll
        for (int i = 0; i < 8; ++i) {
            float4 v0 = make_float4(acc[i][0], acc[i][1], acc[i][2], acc[i][3]);
            float4 v1 = make_float4(acc[i][4], acc[i][5], acc[i][6], acc[i][7]);
            *(float4*)&out[l0 + ty * 8 + i][tx * 8]     = v0;
            *(float4*)&out[l0 + ty * 8 + i][tx * 8 + 4] = v1;
        }
    }
}

// ---------------------------------------------------------------------------
// Fused flash attention: q-tile 128, k-tile 64, 128 threads, 8x8 per thread.
// grid (LQ/128, B*H). smem ~96.3 KB -> 2 CTAs/SM.
// ---------------------------------------------------------------------------
__global__ __launch_bounds__(128) void attn_kernel(const float* __restrict__ mask)
{
    extern __shared__ float sm[];
    float(*sQ)[128] = (float(*)[128])sm;               // [e][q] 32 KB
    float(*sK)[64]  = (float(*)[64])(sm + 8192);       // [e][k] 16 KB
    float(*sV)[64]  = (float(*)[64])(sm + 12288);      // [k][e] 16 KB
    float(*sPT)[128]= (float(*)[128])(sm + 16384);     // [k][q] 32 KB
    float* smask    = sm + 24576;                      // 64

    const int q0  = blockIdx.x * 128;
    const int bh  = blockIdx.y;
    const int b   = bh >> 3;
    const int h   = bh & 7;
    const int tid = threadIdx.x;
    const int ty  = tid >> 3;   // q group
    const int tx  = tid & 7;    // k group (QK) / e group (PV)

    // load sQ[e][q]: 2048 float4
#pragma unroll
    for (int r = 0; r < 16; ++r) {
        int u = tid + r * 128;
        int row = u >> 5, c4 = u & 31;
        *(float4*)&sQ[row][c4 * 4] =
            *(const float4*)&g_qT[bh][row][q0 + c4 * 4];
    }

    float m[8], l[8], o[8][8];
#pragma unroll
    for (int i = 0; i < 8; ++i) {
        m[i] = -1e30f; l[i] = 0.f;
#pragma unroll
        for (int j = 0; j < 8; ++j) o[i][j] = 0.f;
    }

    for (int kt = 0; kt < LK / 64; ++kt) {
        __syncthreads();   // prior-iter reads of sK/sV/sPT done
        // sK[e][k]: 1024 float4
#pragma unroll
        for (int r = 0; r < 8; ++r) {
            int u = tid + r * 128;
            int row = u >> 4, c4 = u & 15;
            *(float4*)&sK[row][c4 * 4] =
                *(const float4*)&g_kT[bh][row][kt * 64 + c4 * 4];
        }
        // sV[k][e]: 1024 float4
#pragma unroll
        for (int r = 0; r < 8; ++r) {
            int u = tid + r * 128;
            int row = u >> 4, c4 = u & 15;
            *(float4*)&sV[row][c4 * 4] =
                *(const float4*)&g_v[bh][kt * 64 + row][c4 * 4];
        }
        if (tid < 64) smask[tid] = mask[(size_t)b * LK + kt * 64 + tid];
        __syncthreads();

        // S = Q^T K  (inner over e = 64)
        float s[8][8];
#pragma unroll
        for (int i = 0; i < 8; ++i)
#pragma unroll
            for (int j = 0; j < 8; ++j) s[i][j] = 0.f;
#pragma unroll
        for (int kk = 0; kk < 64; ++kk) {
            float a[8], bb[8];
            *(float4*)(a)      = *(const float4*)&sQ[kk][ty * 8];
            *(float4*)(a + 4)  = *(const float4*)&sQ[kk][ty * 8 + 4];
            *(float4*)(bb)     = *(const float4*)&sK[kk][tx * 8];
            *(float4*)(bb + 4) = *(const float4*)&sK[kk][tx * 8 + 4];
#pragma unroll
            for (int i = 0; i < 8; ++i)
#pragma unroll
                for (int j = 0; j < 8; ++j) s[i][j] += a[i] * bb[j];
        }

        // mask per key column
#pragma unroll
        for (int j = 0; j < 8; ++j) {
            if (smask[tx * 8 + j] == 0.f) {
#pragma unroll
                for (int i = 0; i < 8; ++i) s[i][j] = -1e30f;
            }
        }

        // online softmax per q row (8 tx lanes per row)
#pragma unroll
        for (int i = 0; i < 8; ++i) {
            float rm = s[i][0];
#pragma unroll
            for (int j = 1; j < 8; ++j) rm = fmaxf(rm, s[i][j]);
            rm = fmaxf(rm, __shfl_xor_sync(0xffffffffu, rm, 4));
            rm = fmaxf(rm, __shfl_xor_sync(0xffffffffu, rm, 2));
            rm = fmaxf(rm, __shfl_xor_sync(0xffffffffu, rm, 1));
            float mn = fmaxf(m[i], rm);
            float sc = __expf(m[i] - mn);
            float rs = 0.f;
#pragma unroll
            for (int j = 0; j < 8; ++j) {
                s[i][j] = __expf(s[i][j] - mn);
                rs += s[i][j];
            }
            rs += __shfl_xor_sync(0xffffffffu, rs, 4);
            rs += __shfl_xor_sync(0xffffffffu, rs, 2);
            rs += __shfl_xor_sync(0xffffffffu, rs, 1);
            l[i] = l[i] * sc + rs;
            m[i] = mn;
#pragma unroll
            for (int j = 0; j < 8; ++j) o[i][j] *= sc;
        }

        __syncthreads();   // all QK reads of sPT region... (sPT distinct; guards write-after-read of prior PV)
        // store P transposed: sPT[k][q]
#pragma unroll
        for (int j = 0; j < 8; ++j) {
            float4 v0 = make_float4(s[0][j], s[1][j], s[2][j], s[3][j]);
            float4 v1 = make_float4(s[4][j], s[5][j], s[6][j], s[7][j]);
            *(float4*)&sPT[tx * 8 + j][ty * 8]     = v0;
            *(float4*)&sPT[tx * 8 + j][ty * 8 + 4] = v1;
        }
        __syncthreads();

        // O += P V  (inner over k = 64)
#pragma unroll
        for (int kk = 0; kk < 64; ++kk) {
            float a[8], bb[8];
            *(float4*)(a)      = *(const float4*)&sPT[kk][ty * 8];
            *(float4*)(a + 4)  = *(const float4*)&sPT[kk][ty * 8 + 4];
            *(float4*)(bb)     = *(const float4*)&sV[kk][tx * 8];
            *(float4*)(bb + 4) = *(const float4*)&sV[kk][tx * 8 + 4];
#pragma unroll
            for (int i = 0; i < 8; ++i)
#pragma unroll
                for (int j = 0; j < 8; ++j) o[i][j] += a[i] * bb[j];
        }
    }

    // epilogue -> g_conc[b*LQ + q][h*64 + e]
#pragma unroll
    for (int i = 0; i < 8; ++i) {
        float inv = 1.f / l[i];
        float4 v0 = make_float4(o[i][0] * inv, o[i][1] * inv,
                                o[i][2] * inv, o[i][3] * inv);
        float4 v1 = make_float4(o[i][4] * inv, o[i][5] * inv,
                                o[i][6] * inv, o[i][7] * inv);
        float* row = g_conc[(size_t)b * LQ + q0 + ty * 8 + i];
        *(float4*)&row[h * 64 + tx * 8]     = v0;
        *(float4*)&row[h * 64 + tx * 8 + 4] = v1;
    }
}

// ---------------------------------------------------------------------------
// LayerNorm over last dim (512), one block (128 threads) per row
// ---------------------------------------------------------------------------
__global__ __launch_bounds__(128) void ln_kernel(
    const float* __restrict__ gamma, const float* __restrict__ beta,
    float* __restrict__ out)
{
    const int row = blockIdx.x;
    const float* x = g_conc[row];
    const int tid = threadIdx.x;

    float v[4];
    float s = 0.f;
#pragma unroll
    for (int i = 0; i < 4; ++i) { v[i] = x[tid + i * 128]; s += v[i]; }

    __shared__ float red1[4];
    __shared__ float red2[4];
#pragma unroll
    for (int off = 16; off >= 1; off >>= 1)
        s += __shfl_xor_sync(0xffffffffu, s, off);
    if ((tid & 31) == 0) red1[tid >> 5] = s;
    __syncthreads();
    float mean = (red1[0] + red1[1] + red1[2] + red1[3]) * (1.f / 512.f);

    float q = 0.f;
#pragma unroll
    for (int i = 0; i < 4; ++i) { float d = v[i] - mean; q += d * d; }
#pragma unroll
    for (int off = 16; off >= 1; off >>= 1)
        q += __shfl_xor_sync(0xffffffffu, q, off);
    if ((tid & 31) == 0) red2[tid >> 5] = q;
    __syncthreads();
    float var  = (red2[0] + red2[1] + red2[2] + red2[3]) * (1.f / 512.f);
    float rstd = rsqrtf(var + 1e-14f);
    float g = gamma[0], be = beta[0];
#pragma unroll
    for (int i = 0; i < 4; ++i)
        out[(size_t)row * 512 + tid + i * 128] = (v[i] - mean) * rstd * g + be;
}

// ---------------------------------------------------------------------------
extern "C" void kernel_launch(void* const* d_in, const int* in_sizes, int n_in,
                              void* d_out, int out_size)
{
    const float* query = (const float*)d_in[0];
    const float* key_t = (const float*)d_in[1];
    const float* value = (const float*)d_in[2];
    const float* mask  = (const float*)d_in[3];
    const float* Wq    = (const float*)d_in[4];
    const float* Wk    = (const float*)d_in[5];
    const float* Wv    = (const float*)d_in[6];
    const float* gamma = (const float*)d_in[7];
    const float* beta  = (const float*)d_in[8];
    float* out = (float*)d_out;

    transpose_kernel<<<dim3(DD / 32, LQ / 32, 3 * B), dim3(32, 8)>>>(
        query, key_t, value);

    dim3 pg(LQ / 128, H, B);
    proj_kernel<<<pg, 128>>>(Wq, 0);
    proj_kernel<<<pg, 128>>>(Wk, 1);
    proj_kernel<<<pg, 128>>>(Wv, 2);

    const int attn_smem = (24576 + 64) * (int)sizeof(float);  // 98560 B
    static int smem_set = 0;
    if (!smem_set) {
        cudaFuncSetAttribute(attn_kernel,
                             cudaFuncAttributeMaxDynamicSharedMemorySize,
                             attn_smem);
        smem_set = 1;
    }
    attn_kernel<<<dim3(LQ / 128, B * H), 128, attn_smem>>>(mask);

    ln_kernel<<<B * LQ, 128>>>(gamma, beta, out);
}

// round 4
// speedup vs baseline: 2.1886x; 2.1886x over previous
#include <cuda_runtime.h>
#include <cuda_bf16.h>
#include <math.h>
#include <stdint.h>

#define B   8
#define LQ  1024
#define LK  1024
#define DD  512
#define H   8

// ---------------------------------------------------------------------------
// Device scratch (static globals — allocation-guard safe)
// ---------------------------------------------------------------------------
#define XN (8ull*1024*512)
__device__ __nv_bfloat16 g_xh[3*XN];               // inputs hi  (25MB)
__device__ __nv_bfloat16 g_xl[3*XN];               // inputs lo  (25MB)
__device__ __nv_bfloat16 g_wth[3ull*8*64*512];     // W^T hi [which][h][e][d]
__device__ __nv_bfloat16 g_wtl[3ull*8*64*512];     // W^T lo
__device__ float g_q[(size_t)B*H*LQ*64];           // [bh][l][e]
__device__ float g_k[(size_t)B*H*LK*64];
__device__ float g_v[(size_t)B*H*LK*64];
__device__ float g_conc[(size_t)B*LQ*512];

// ---------------------------------------------------------------------------
// mma.sync m16n8k16 bf16 (row.col), f32 accum
// ---------------------------------------------------------------------------
#define MMA16816(c, a0, a1, a2, a3, b0, b1)                                   \
    asm volatile(                                                             \
        "mma.sync.aligned.m16n8k16.row.col.f32.bf16.bf16.f32 "                \
        "{%0,%1,%2,%3}, {%4,%5,%6,%7}, {%8,%9}, {%0,%1,%2,%3};"               \
        : "+f"((c)[0]), "+f"((c)[1]), "+f"((c)[2]), "+f"((c)[3])              \
        : "r"(a0), "r"(a1), "r"(a2), "r"(a3), "r"(b0), "r"(b1))

// ---------------------------------------------------------------------------
// Convert inputs fp32 -> bf16 hi/lo (same layout)
// ---------------------------------------------------------------------------
__global__ __launch_bounds__(256) void convert_x_kernel(
    const float* __restrict__ q, const float* __restrict__ k,
    const float* __restrict__ v)
{
    const int which = blockIdx.y;
    const float* src = (which == 0) ? q : (which == 1) ? k : v;
    size_t i4 = (size_t)blockIdx.x * 256 + threadIdx.x;
    float4 x = ((const float4*)src)[i4];
    size_t base = (size_t)which * XN + i4 * 4;

    __nv_bfloat16 h0 = __float2bfloat16(x.x);
    __nv_bfloat16 h1 = __float2bfloat16(x.y);
    __nv_bfloat16 h2 = __float2bfloat16(x.z);
    __nv_bfloat16 h3 = __float2bfloat16(x.w);
    ((__nv_bfloat162*)(g_xh + base))[0] = __halves2bfloat162(h0, h1);
    ((__nv_bfloat162*)(g_xh + base))[1] = __halves2bfloat162(h2, h3);
    __nv_bfloat16 l0 = __float2bfloat16(x.x - __bfloat162float(h0));
    __nv_bfloat16 l1 = __float2bfloat16(x.y - __bfloat162float(h1));
    __nv_bfloat16 l2 = __float2bfloat16(x.z - __bfloat162float(h2));
    __nv_bfloat16 l3 = __float2bfloat16(x.w - __bfloat162float(h3));
    ((__nv_bfloat162*)(g_xl + base))[0] = __halves2bfloat162(l0, l1);
    ((__nv_bfloat162*)(g_xl + base))[1] = __halves2bfloat162(l2, l3);
}

// ---------------------------------------------------------------------------
// Convert + transpose weights: W[h][d][e] fp32 -> g_wt{h,l}[which][h][e][d]
// ---------------------------------------------------------------------------
__global__ __launch_bounds__(256) void convert_w_kernel(
    const float* __restrict__ Wq, const float* __restrict__ Wk,
    const float* __restrict__ Wv)
{
    const int which = blockIdx.x;
    const int h     = blockIdx.y;
    const float* W = ((which == 0) ? Wq : (which == 1) ? Wk : Wv) + (size_t)h * DD * 64;
    size_t obase = ((size_t)(which * 8 + h)) * 64 * 512;
    for (int it = 0; it < 128; ++it) {
        int idx = it * 256 + threadIdx.x;
        int e = idx & 63, d = idx >> 6;
        float x = W[(size_t)d * 64 + e];
        __nv_bfloat16 hi = __float2bfloat16(x);
        g_wth[obase + (size_t)e * 512 + d] = hi;
        g_wtl[obase + (size_t)e * 512 + d] =
            __float2bfloat16(x - __bfloat162float(hi));
    }
}

// ---------------------------------------------------------------------------
// Projection via mma.sync: out[l][e] = sum_d X[l][d] W[d][e], split bf16.
// grid (LQ/128, H, 3*B), 256 threads (8 warps). M-tile 128, N 64, K-chunk 64.
// smem rows padded to 72 bf16 (144 B): uint4-aligned, LDS conflict-free.
// ---------------------------------------------------------------------------
#define PLD 72
#define PROJ_SMEM ((128 * PLD * 2 + 64 * PLD * 2) * 2)  // 55296 bytes

__global__ __launch_bounds__(256) void proj_mma_kernel()
{
    extern __shared__ __nv_bfloat16 psm[];
    __nv_bfloat16* sAh = psm;                 // 128*72
    __nv_bfloat16* sAl = psm + 128 * PLD;
    __nv_bfloat16* sBh = psm + 256 * PLD;     // 64*72
    __nv_bfloat16* sBl = psm + 256 * PLD + 64 * PLD;

    const int tid  = threadIdx.x;
    const int warp = tid >> 5;
    const int lane = tid & 31;
    const int r    = lane >> 2;        // 0..7
    const int cg   = (lane & 3) * 2;   // 0,2,4,6
    const int m0   = warp * 16;

    const int l0 = blockIdx.x * 128;
    const int h  = blockIdx.y;
    const int z  = blockIdx.z;
    const int which = z >> 3, b = z & 7;

    const __nv_bfloat16* xh = g_xh + (size_t)which * XN + ((size_t)b * 1024 + l0) * 512;
    const __nv_bfloat16* xl = g_xl + (size_t)which * XN + ((size_t)b * 1024 + l0) * 512;
    const __nv_bfloat16* wh = g_wth + ((size_t)(which * 8 + h)) * 64 * 512;
    const __nv_bfloat16* wl = g_wtl + ((size_t)(which * 8 + h)) * 64 * 512;

    float c[8][4];
#pragma unroll
    for (int n = 0; n < 8; ++n)
#pragma unroll
        for (int j = 0; j < 4; ++j) c[n][j] = 0.f;

    for (int dt = 0; dt < 8; ++dt) {
        __syncthreads();
        // A tiles: 128 rows x 64 bf16 -> 1024 uint4 each (hi, lo)
#pragma unroll
        for (int rr = 0; rr < 4; ++rr) {
            int u = tid + rr * 256;
            int row = u >> 3, cc = u & 7;
            size_t so = (size_t)row * 512 + dt * 64 + cc * 8;
            int de = row * PLD + cc * 8;
            *(uint4*)(sAh + de) = *(const uint4*)(xh + so);
            *(uint4*)(sAl + de) = *(const uint4*)(xl + so);
        }
        // B tiles: 64 rows (e) x 64 bf16 -> 512 uint4 each
#pragma unroll
        for (int rr = 0; rr < 2; ++rr) {
            int u = tid + rr * 256;
            int e = u >> 3, cc = u & 7;
            size_t so = (size_t)e * 512 + dt * 64 + cc * 8;
            int de = e * PLD + cc * 8;
            *(uint4*)(sBh + de) = *(const uint4*)(wh + so);
            *(uint4*)(sBl + de) = *(const uint4*)(wl + so);
        }
        __syncthreads();

        // A fragments for all 4 k-steps (hi & lo)
        uint32_t ah[16], al[16];
#pragma unroll
        for (int ks = 0; ks < 4; ++ks) {
            int ro = (m0 + r) * PLD + ks * 16 + cg;
            ah[ks * 4 + 0] = *(const uint32_t*)(sAh + ro);
            ah[ks * 4 + 1] = *(const uint32_t*)(sAh + ro + 8 * PLD);
            ah[ks * 4 + 2] = *(const uint32_t*)(sAh + ro + 8);
            ah[ks * 4 + 3] = *(const uint32_t*)(sAh + ro + 8 * PLD + 8);
            al[ks * 4 + 0] = *(const uint32_t*)(sAl + ro);
            al[ks * 4 + 1] = *(const uint32_t*)(sAl + ro + 8 * PLD);
            al[ks * 4 + 2] = *(const uint32_t*)(sAl + ro + 8);
            al[ks * 4 + 3] = *(const uint32_t*)(sAl + ro + 8 * PLD + 8);
        }

#pragma unroll
        for (int n = 0; n < 8; ++n) {
            int bo = (n * 8 + r) * PLD + cg;
#pragma unroll
            for (int ks = 0; ks < 4; ++ks) {
                uint32_t bh0 = *(const uint32_t*)(sBh + bo + ks * 16);
                uint32_t bh1 = *(const uint32_t*)(sBh + bo + ks * 16 + 8);
                uint32_t bl0 = *(const uint32_t*)(sBl + bo + ks * 16);
                uint32_t bl1 = *(const uint32_t*)(sBl + bo + ks * 16 + 8);
                MMA16816(c[n], ah[ks*4+0], ah[ks*4+1], ah[ks*4+2], ah[ks*4+3], bh0, bh1);
                MMA16816(c[n], ah[ks*4+0], ah[ks*4+1], ah[ks*4+2], ah[ks*4+3], bl0, bl1);
                MMA16816(c[n], al[ks*4+0], al[ks*4+1], al[ks*4+2], al[ks*4+3], bh0, bh1);
            }
        }
    }

    float* out = (which == 0) ? g_q : (which == 1) ? g_k : g_v;
    size_t rowbase = ((size_t)(b * 8 + h) * 1024 + l0 + m0 + r);
#pragma unroll
    for (int n = 0; n < 8; ++n) {
        *(float2*)(out + rowbase * 64 + n * 8 + cg)       = make_float2(c[n][0], c[n][1]);
        *(float2*)(out + (rowbase + 8) * 64 + n * 8 + cg) = make_float2(c[n][2], c[n][3]);
    }
}

// ---------------------------------------------------------------------------
// Flash attention: q-tile 128, k-tile 64, 256 threads, 8x4 per thread.
// ---------------------------------------------------------------------------
#define SQ_STR 132
#define SK_STR 68
#define OFF_SQ   0
#define OFF_SK   8448
#define OFF_SV   12800
#define OFF_SPT  16896
#define OFF_MSK  25344
#define ATTN_SMEM ((25344 + 64) * 4)

__global__ __launch_bounds__(256, 2) void attn_kernel(const float* __restrict__ mask)
{
    extern __shared__ float sm[];
    float* sQ    = sm + OFF_SQ;    // [e][q] stride 132
    float* sK    = sm + OFF_SK;    // [e][k] stride 68
    float* sV    = sm + OFF_SV;    // [k][e] stride 64
    float* sPT   = sm + OFF_SPT;   // [k][q] stride 132
    float* smask = sm + OFF_MSK;

    const int q0  = blockIdx.x * 128;
    const int bh  = blockIdx.y;
    const int b   = bh >> 3;
    const int hh  = bh & 7;
    const int tid = threadIdx.x;
    const int ty  = tid >> 4;   // 0..15: q group of 8
    const int tx  = tid & 15;   // 0..15: k group of 4 / e group of 4

    const float* Qb = g_q + ((size_t)bh * LQ + q0) * 64;
    const float* Kb = g_k + (size_t)bh * LK * 64;
    const float* Vb = g_v + (size_t)bh * LK * 64;

    // sQ[e][q] (transpose on load)
#pragma unroll
    for (int r = 0; r < 8; ++r) {
        int u = tid + r * 256;
        int row = u >> 4, c4 = u & 15;
        float4 v = *(const float4*)(Qb + (size_t)row * 64 + c4 * 4);
        sQ[(c4 * 4 + 0) * SQ_STR + row] = v.x;
        sQ[(c4 * 4 + 1) * SQ_STR + row] = v.y;
        sQ[(c4 * 4 + 2) * SQ_STR + row] = v.z;
        sQ[(c4 * 4 + 3) * SQ_STR + row] = v.w;
    }

    float m[8], l[8], o[8][4];
#pragma unroll
    for (int i = 0; i < 8; ++i) {
        m[i] = -1e30f; l[i] = 0.f;
#pragma unroll
        for (int j = 0; j < 4; ++j) o[i][j] = 0.f;
    }

    for (int kt = 0; kt < LK / 64; ++kt) {
        __syncthreads();
        // sK[e][k]
#pragma unroll
        for (int r = 0; r < 4; ++r) {
            int u = tid + r * 256;
            int row = u >> 4, c4 = u & 15;
            float4 v = *(const float4*)(Kb + (size_t)(kt * 64 + row) * 64 + c4 * 4);
            sK[(c4 * 4 + 0) * SK_STR + row] = v.x;
            sK[(c4 * 4 + 1) * SK_STR + row] = v.y;
            sK[(c4 * 4 + 2) * SK_STR + row] = v.z;
            sK[(c4 * 4 + 3) * SK_STR + row] = v.w;
        }
        // sV[k][e]
#pragma unroll
        for (int r = 0; r < 4; ++r) {
            int u = tid + r * 256;
            int row = u >> 4, c4 = u & 15;
            *(float4*)(sV + row * 64 + c4 * 4) =
                *(const float4*)(Vb + (size_t)(kt * 64 + row) * 64 + c4 * 4);
        }
        if (tid < 64) smask[tid] = mask[(size_t)b * LK + kt * 64 + tid];
        __syncthreads();

        // S = Q^T K
        float s[8][4];
#pragma unroll
        for (int i = 0; i < 8; ++i)
#pragma unroll
            for (int j = 0; j < 4; ++j) s[i][j] = 0.f;
#pragma unroll 8
        for (int kk = 0; kk < 64; ++kk) {
            float a[8], bb[4];
            *(float4*)(a)     = *(const float4*)(sQ + kk * SQ_STR + ty * 8);
            *(float4*)(a + 4) = *(const float4*)(sQ + kk * SQ_STR + ty * 8 + 4);
            *(float4*)(bb)    = *(const float4*)(sK + kk * SK_STR + tx * 4);
#pragma unroll
            for (int i = 0; i < 8; ++i)
#pragma unroll
                for (int j = 0; j < 4; ++j) s[i][j] += a[i] * bb[j];
        }

        // mask per key column
#pragma unroll
        for (int j = 0; j < 4; ++j) {
            if (smask[tx * 4 + j] == 0.f) {
#pragma unroll
                for (int i = 0; i < 8; ++i) s[i][j] = -1e30f;
            }
        }

        // online softmax per q row (16 tx lanes per row)
#pragma unroll
        for (int i = 0; i < 8; ++i) {
            float rm = fmaxf(fmaxf(s[i][0], s[i][1]), fmaxf(s[i][2], s[i][3]));
#pragma unroll
            for (int off = 8; off >= 1; off >>= 1)
                rm = fmaxf(rm, __shfl_xor_sync(0xffffffffu, rm, off));
            float mn = fmaxf(m[i], rm);
            float sc = __expf(m[i] - mn);
            float rs = 0.f;
#pragma unroll
            for (int j = 0; j < 4; ++j) {
                s[i][j] = __expf(s[i][j] - mn);
                rs += s[i][j];
            }
#pragma unroll
            for (int off = 8; off >= 1; off >>= 1)
                rs += __shfl_xor_sync(0xffffffffu, rs, off);
            l[i] = l[i] * sc + rs;
            m[i] = mn;
#pragma unroll
            for (int j = 0; j < 4; ++j) o[i][j] *= sc;
        }

        // stage P transposed: sPT[k][q]
#pragma unroll
        for (int j = 0; j < 4; ++j) {
            float4 v0 = make_float4(s[0][j], s[1][j], s[2][j], s[3][j]);
            float4 v1 = make_float4(s[4][j], s[5][j], s[6][j], s[7][j]);
            *(float4*)(sPT + (tx * 4 + j) * SQ_STR + ty * 8)     = v0;
            *(float4*)(sPT + (tx * 4 + j) * SQ_STR + ty * 8 + 4) = v1;
        }
        __syncthreads();

        // O += P V
#pragma unroll 8
        for (int kk = 0; kk < 64; ++kk) {
            float a[8], bb[4];
            *(float4*)(a)     = *(const float4*)(sPT + kk * SQ_STR + ty * 8);
            *(float4*)(a + 4) = *(const float4*)(sPT + kk * SQ_STR + ty * 8 + 4);
            *(float4*)(bb)    = *(const float4*)(sV + kk * 64 + tx * 4);
#pragma unroll
            for (int i = 0; i < 8; ++i)
#pragma unroll
                for (int j = 0; j < 4; ++j) o[i][j] += a[i] * bb[j];
        }
    }

    // epilogue
#pragma unroll
    for (int i = 0; i < 8; ++i) {
        float inv = 1.f / l[i];
        float4 v = make_float4(o[i][0] * inv, o[i][1] * inv,
                               o[i][2] * inv, o[i][3] * inv);
        float* row = g_conc + ((size_t)b * LQ + q0 + ty * 8 + i) * 512;
        *(float4*)(row + hh * 64 + tx * 4) = v;
    }
}

// ---------------------------------------------------------------------------
// LayerNorm over last dim (512)
// ---------------------------------------------------------------------------
__global__ __launch_bounds__(128) void ln_kernel(
    const float* __restrict__ gamma, const float* __restrict__ beta,
    float* __restrict__ out)
{
    const int row = blockIdx.x;
    const float* x = g_conc + (size_t)row * 512;
    const int tid = threadIdx.x;

    float v[4];
    float s = 0.f;
#pragma unroll
    for (int i = 0; i < 4; ++i) { v[i] = x[tid + i * 128]; s += v[i]; }

    __shared__ float red1[4];
    __shared__ float red2[4];
#pragma unroll
    for (int off = 16; off >= 1; off >>= 1)
        s += __shfl_xor_sync(0xffffffffu, s, off);
    if ((tid & 31) == 0) red1[tid >> 5] = s;
    __syncthreads();
    float mean = (red1[0] + red1[1] + red1[2] + red1[3]) * (1.f / 512.f);

    float q = 0.f;
#pragma unroll
    for (int i = 0; i < 4; ++i) { float d = v[i] - mean; q += d * d; }
#pragma unroll
    for (int off = 16; off >= 1; off >>= 1)
        q += __shfl_xor_sync(0xffffffffu, q, off);
    if ((tid & 31) == 0) red2[tid >> 5] = q;
    __syncthreads();
    float var  = (red2[0] + red2[1] + red2[2] + red2[3]) * (1.f / 512.f);
    float rstd = rsqrtf(var + 1e-14f);
    float g = gamma[0], be = beta[0];
#pragma unroll
    for (int i = 0; i < 4; ++i)
        out[(size_t)row * 512 + tid + i * 128] = (v[i] - mean) * rstd * g + be;
}

// ---------------------------------------------------------------------------
extern "C" void kernel_launch(void* const* d_in, const int* in_sizes, int n_in,
                              void* d_out, int out_size)
{
    const float* query = (const float*)d_in[0];
    const float* key_t = (const float*)d_in[1];
    const float* value = (const float*)d_in[2];
    const float* mask  = (const float*)d_in[3];
    const float* Wq    = (const float*)d_in[4];
    const float* Wk    = (const float*)d_in[5];
    const float* Wv    = (const float*)d_in[6];
    const float* gamma = (const float*)d_in[7];
    const float* beta  = (const float*)d_in[8];
    float* out = (float*)d_out;

    static int attr_set = 0;
    if (!attr_set) {
        cudaFuncSetAttribute(proj_mma_kernel,
                             cudaFuncAttributeMaxDynamicSharedMemorySize, PROJ_SMEM);
        cudaFuncSetAttribute(attn_kernel,
                             cudaFuncAttributeMaxDynamicSharedMemorySize, ATTN_SMEM);
        attr_set = 1;
    }

    convert_x_kernel<<<dim3(4096, 3), 256>>>(query, key_t, value);
    convert_w_kernel<<<dim3(3, 8), 256>>>(Wq, Wk, Wv);

    proj_mma_kernel<<<dim3(LQ / 128, H, 3 * B), 256, PROJ_SMEM>>>();

    attn_kernel<<<dim3(LQ / 128, B * H), 256, ATTN_SMEM>>>(mask);

    ln_kernel<<<B * LQ, 128>>>(gamma, beta, out);
}

// round 5
// speedup vs baseline: 3.5235x; 1.6100x over previous
#include <cuda_runtime.h>
#include <cuda_bf16.h>
#include <math.h>
#include <stdint.h>

#define B   8
#define LQ  1024
#define LK  1024
#define DD  512
#define H   8

// ---------------------------------------------------------------------------
// Device scratch (static globals — allocation-guard safe)
// ---------------------------------------------------------------------------
#define XN (8ull*1024*512)
__device__ __nv_bfloat16 g_xh[3*XN];               // inputs hi
__device__ __nv_bfloat16 g_xl[3*XN];               // inputs lo
__device__ __nv_bfloat16 g_wth[3ull*8*64*512];     // W^T hi [which][h][e][d]
__device__ __nv_bfloat16 g_wtl[3ull*8*64*512];     // W^T lo
__device__ __nv_bfloat16 g_oh[3ull*64*1024*64];    // proj out hi [which][bh][l][e]
__device__ __nv_bfloat16 g_ol[3ull*64*1024*64];    // proj out lo
__device__ __nv_bfloat16 g_vth[64ull*64*1024];     // V^T hi [bh][e][l]
__device__ __nv_bfloat16 g_vtl[64ull*64*1024];     // V^T lo
__device__ float g_conc[(size_t)B*LQ*512];

// ---------------------------------------------------------------------------
// mma.sync m16n8k16 bf16 (row.col), f32 accum
// ---------------------------------------------------------------------------
#define MMA16816(c, a0, a1, a2, a3, b0, b1)                                   \
    asm volatile(                                                             \
        "mma.sync.aligned.m16n8k16.row.col.f32.bf16.bf16.f32 "                \
        "{%0,%1,%2,%3}, {%4,%5,%6,%7}, {%8,%9}, {%0,%1,%2,%3};"               \
        : "+f"((c)[0]), "+f"((c)[1]), "+f"((c)[2]), "+f"((c)[3])              \
        : "r"(a0), "r"(a1), "r"(a2), "r"(a3), "r"(b0), "r"(b1))

__device__ __forceinline__ uint32_t packbf(float lo, float hi) {
    uint32_t d;
    asm("cvt.rn.bf16x2.f32 %0, %1, %2;" : "=r"(d) : "f"(hi), "f"(lo));
    return d;
}
__device__ __forceinline__ float bfres(float x) {
    return x - __bfloat162float(__float2bfloat16_rn(x));
}

// ---------------------------------------------------------------------------
// Convert inputs fp32 -> bf16 hi/lo
// ---------------------------------------------------------------------------
__global__ __launch_bounds__(256) void convert_x_kernel(
    const float* __restrict__ q, const float* __restrict__ k,
    const float* __restrict__ v)
{
    const int which = blockIdx.y;
    const float* src = (which == 0) ? q : (which == 1) ? k : v;
    size_t i4 = (size_t)blockIdx.x * 256 + threadIdx.x;
    float4 x = ((const float4*)src)[i4];
    size_t base = (size_t)which * XN + i4 * 4;

    __nv_bfloat16 h0 = __float2bfloat16(x.x);
    __nv_bfloat16 h1 = __float2bfloat16(x.y);
    __nv_bfloat16 h2 = __float2bfloat16(x.z);
    __nv_bfloat16 h3 = __float2bfloat16(x.w);
    ((__nv_bfloat162*)(g_xh + base))[0] = __halves2bfloat162(h0, h1);
    ((__nv_bfloat162*)(g_xh + base))[1] = __halves2bfloat162(h2, h3);
    ((__nv_bfloat162*)(g_xl + base))[0] = __halves2bfloat162(
        __float2bfloat16(x.x - __bfloat162float(h0)),
        __float2bfloat16(x.y - __bfloat162float(h1)));
    ((__nv_bfloat162*)(g_xl + base))[1] = __halves2bfloat162(
        __float2bfloat16(x.z - __bfloat162float(h2)),
        __float2bfloat16(x.w - __bfloat162float(h3)));
}

// ---------------------------------------------------------------------------
// Convert + transpose weights: W[h][d][e] fp32 -> g_wt{h,l}[which][h][e][d]
// ---------------------------------------------------------------------------
__global__ __launch_bounds__(256) void convert_w_kernel(
    const float* __restrict__ Wq, const float* __restrict__ Wk,
    const float* __restrict__ Wv)
{
    const int which = blockIdx.x;
    const int h     = blockIdx.y;
    const float* W = ((which == 0) ? Wq : (which == 1) ? Wk : Wv) + (size_t)h * DD * 64;
    size_t obase = ((size_t)(which * 8 + h)) * 64 * 512;
    for (int it = 0; it < 128; ++it) {
        int idx = it * 256 + threadIdx.x;
        int e = idx & 63, d = idx >> 6;
        float x = W[(size_t)d * 64 + e];
        __nv_bfloat16 hi = __float2bfloat16(x);
        g_wth[obase + (size_t)e * 512 + d] = hi;
        g_wtl[obase + (size_t)e * 512 + d] =
            __float2bfloat16(x - __bfloat162float(hi));
    }
}

// ---------------------------------------------------------------------------
// Projection via mma.sync: out[l][e] = sum_d X[l][d] W[d][e], split bf16.
// grid (LQ/128, H, 3*B), 256 threads. Writes bf16 hi/lo to g_oh/g_ol.
// ---------------------------------------------------------------------------
#define PLD 72
#define PROJ_SMEM ((128 * PLD * 2 + 64 * PLD * 2) * 2)  // 55296 bytes

__global__ __launch_bounds__(256) void proj_mma_kernel()
{
    extern __shared__ __nv_bfloat16 psm[];
    __nv_bfloat16* sAh = psm;
    __nv_bfloat16* sAl = psm + 128 * PLD;
    __nv_bfloat16* sBh = psm + 256 * PLD;
    __nv_bfloat16* sBl = psm + 256 * PLD + 64 * PLD;

    const int tid  = threadIdx.x;
    const int warp = tid >> 5;
    const int lane = tid & 31;
    const int r    = lane >> 2;
    const int cg   = (lane & 3) * 2;
    const int mw   = warp * 16;

    const int l0 = blockIdx.x * 128;
    const int h  = blockIdx.y;
    const int z  = blockIdx.z;
    const int which = z >> 3, b = z & 7;

    const __nv_bfloat16* xh = g_xh + (size_t)which * XN + ((size_t)b * 1024 + l0) * 512;
    const __nv_bfloat16* xl = g_xl + (size_t)which * XN + ((size_t)b * 1024 + l0) * 512;
    const __nv_bfloat16* wh = g_wth + ((size_t)(which * 8 + h)) * 64 * 512;
    const __nv_bfloat16* wl = g_wtl + ((size_t)(which * 8 + h)) * 64 * 512;

    float c[8][4];
#pragma unroll
    for (int n = 0; n < 8; ++n)
#pragma unroll
        for (int j = 0; j < 4; ++j) c[n][j] = 0.f;

    for (int dt = 0; dt < 8; ++dt) {
        __syncthreads();
#pragma unroll
        for (int rr = 0; rr < 4; ++rr) {
            int u = tid + rr * 256;
            int row = u >> 3, cc = u & 7;
            size_t so = (size_t)row * 512 + dt * 64 + cc * 8;
            int de = row * PLD + cc * 8;
            *(uint4*)(sAh + de) = *(const uint4*)(xh + so);
            *(uint4*)(sAl + de) = *(const uint4*)(xl + so);
        }
#pragma unroll
        for (int rr = 0; rr < 2; ++rr) {
            int u = tid + rr * 256;
            int e = u >> 3, cc = u & 7;
            size_t so = (size_t)e * 512 + dt * 64 + cc * 8;
            int de = e * PLD + cc * 8;
            *(uint4*)(sBh + de) = *(const uint4*)(wh + so);
            *(uint4*)(sBl + de) = *(const uint4*)(wl + so);
        }
        __syncthreads();

#pragma unroll
        for (int ks = 0; ks < 4; ++ks) {
            int ro = (mw + r) * PLD + ks * 16 + cg;
            uint32_t ah0 = *(const uint32_t*)(sAh + ro);
            uint32_t ah1 = *(const uint32_t*)(sAh + ro + 8 * PLD);
            uint32_t ah2 = *(const uint32_t*)(sAh + ro + 8);
            uint32_t ah3 = *(const uint32_t*)(sAh + ro + 8 * PLD + 8);
            uint32_t al0 = *(const uint32_t*)(sAl + ro);
            uint32_t al1 = *(const uint32_t*)(sAl + ro + 8 * PLD);
            uint32_t al2 = *(const uint32_t*)(sAl + ro + 8);
            uint32_t al3 = *(const uint32_t*)(sAl + ro + 8 * PLD + 8);
#pragma unroll
            for (int n = 0; n < 8; ++n) {
                int bo = (n * 8 + r) * PLD + ks * 16 + cg;
                uint32_t bh0 = *(const uint32_t*)(sBh + bo);
                uint32_t bh1 = *(const uint32_t*)(sBh + bo + 8);
                uint32_t bl0 = *(const uint32_t*)(sBl + bo);
                uint32_t bl1 = *(const uint32_t*)(sBl + bo + 8);
                MMA16816(c[n], ah0, ah1, ah2, ah3, bh0, bh1);
                MMA16816(c[n], ah0, ah1, ah2, ah3, bl0, bl1);
                MMA16816(c[n], al0, al1, al2, al3, bh0, bh1);
            }
        }
    }

    size_t rowbase = ((size_t)(which * 64 + b * 8 + h) * 1024 + l0 + mw + r) * 64;
#pragma unroll
    for (int n = 0; n < 8; ++n) {
        *(uint32_t*)(g_oh + rowbase + n * 8 + cg) = packbf(c[n][0], c[n][1]);
        *(uint32_t*)(g_ol + rowbase + n * 8 + cg) =
            packbf(bfres(c[n][0]), bfres(c[n][1]));
        *(uint32_t*)(g_oh + rowbase + 8 * 64 + n * 8 + cg) = packbf(c[n][2], c[n][3]);
        *(uint32_t*)(g_ol + rowbase + 8 * 64 + n * 8 + cg) =
            packbf(bfres(c[n][2]), bfres(c[n][3]));
    }
}

// ---------------------------------------------------------------------------
// Transpose V hi/lo: g_oh/g_ol[2][bh][l][e] -> g_vth/g_vtl[bh][e][l]
// grid (32, 2, 64), block (32, 8)
// ---------------------------------------------------------------------------
__global__ __launch_bounds__(256) void vt_kernel()
{
    __shared__ __nv_bfloat16 t[32][33];
    const int bh = blockIdx.z;
    const int l0 = blockIdx.x * 32;
    const int e0 = blockIdx.y * 32;
    const int x = threadIdx.x, y = threadIdx.y;

    const __nv_bfloat16* srch = g_oh + ((size_t)(2 * 64 + bh) * 1024) * 64;
    const __nv_bfloat16* srcl = g_ol + ((size_t)(2 * 64 + bh) * 1024) * 64;
    __nv_bfloat16* dsth = g_vth + (size_t)bh * 64 * 1024;
    __nv_bfloat16* dstl = g_vtl + (size_t)bh * 64 * 1024;

#pragma unroll
    for (int rr = 0; rr < 4; ++rr)
        t[y + 8 * rr][x] = srch[(size_t)(l0 + y + 8 * rr) * 64 + e0 + x];
    __syncthreads();
#pragma unroll
    for (int rr = 0; rr < 4; ++rr)
        dsth[(size_t)(e0 + y + 8 * rr) * 1024 + l0 + x] = t[x][y + 8 * rr];
    __syncthreads();
#pragma unroll
    for (int rr = 0; rr < 4; ++rr)
        t[y + 8 * rr][x] = srcl[(size_t)(l0 + y + 8 * rr) * 64 + e0 + x];
    __syncthreads();
#pragma unroll
    for (int rr = 0; rr < 4; ++rr)
        dstl[(size_t)(e0 + y + 8 * rr) * 1024 + l0 + x] = t[x][y + 8 * rr];
}

// ---------------------------------------------------------------------------
// Flash attention via mma.sync. 128 q/CTA (8 warps x m16), 64-key tiles.
// ---------------------------------------------------------------------------
#define OQH 0
#define OQL 9216
#define OKH 18432
#define OKL 23040
#define OVH 27648
#define OVL 32256
#define OMSK_BYTES 73728
#define ATTN_SMEM 73984

__global__ __launch_bounds__(256, 2) void attn_mma_kernel(const float* __restrict__ mask)
{
    extern __shared__ __nv_bfloat16 sb[];
    __nv_bfloat16* sQh = sb + OQH;   // [128][72]
    __nv_bfloat16* sQl = sb + OQL;
    __nv_bfloat16* sKh = sb + OKH;   // [64][72]
    __nv_bfloat16* sKl = sb + OKL;
    __nv_bfloat16* sVh = sb + OVH;   // [64 e][72 keys] (V^T)
    __nv_bfloat16* sVl = sb + OVL;
    float* smask = (float*)((char*)sb + OMSK_BYTES);

    const int tid  = threadIdx.x;
    const int warp = tid >> 5;
    const int lane = tid & 31;
    const int r    = lane >> 2;
    const int cg   = (lane & 3) * 2;
    const int mw   = warp * 16;

    const int q0 = blockIdx.x * 128;
    const int bh = blockIdx.y;
    const int b  = bh >> 3;
    const int hh = bh & 7;

    const __nv_bfloat16* Qh = g_oh + ((size_t)(0 * 64 + bh) * 1024 + q0) * 64;
    const __nv_bfloat16* Ql = g_ol + ((size_t)(0 * 64 + bh) * 1024 + q0) * 64;
    const __nv_bfloat16* Kh = g_oh + ((size_t)(1 * 64 + bh) * 1024) * 64;
    const __nv_bfloat16* Kl = g_ol + ((size_t)(1 * 64 + bh) * 1024) * 64;
    const __nv_bfloat16* Vth = g_vth + (size_t)bh * 64 * 1024;
    const __nv_bfloat16* Vtl = g_vtl + (size_t)bh * 64 * 1024;

    // stage Q once: [128][64] -> [128][72]
#pragma unroll
    for (int rr = 0; rr < 4; ++rr) {
        int u = tid + rr * 256;
        int row = u >> 3, c8 = (u & 7) * 8;
        *(uint4*)(sQh + row * 72 + c8) = *(const uint4*)(Qh + (size_t)row * 64 + c8);
        *(uint4*)(sQl + row * 72 + c8) = *(const uint4*)(Ql + (size_t)row * 64 + c8);
    }

    float m[2], l[2], o[8][4];
    m[0] = m[1] = -1e30f;
    l[0] = l[1] = 0.f;
#pragma unroll
    for (int n = 0; n < 8; ++n)
#pragma unroll
        for (int j = 0; j < 4; ++j) o[n][j] = 0.f;

    for (int kt = 0; kt < 16; ++kt) {
        __syncthreads();
#pragma unroll
        for (int rr = 0; rr < 2; ++rr) {
            int u = tid + rr * 256;
            int row = u >> 3, c8 = (u & 7) * 8;
            *(uint4*)(sKh + row * 72 + c8) =
                *(const uint4*)(Kh + (size_t)(kt * 64 + row) * 64 + c8);
            *(uint4*)(sKl + row * 72 + c8) =
                *(const uint4*)(Kl + (size_t)(kt * 64 + row) * 64 + c8);
            *(uint4*)(sVh + row * 72 + c8) =
                *(const uint4*)(Vth + (size_t)row * 1024 + kt * 64 + c8);
            *(uint4*)(sVl + row * 72 + c8) =
                *(const uint4*)(Vtl + (size_t)row * 1024 + kt * 64 + c8);
        }
        if (tid < 64) smask[tid] = mask[(size_t)b * LK + kt * 64 + tid];
        __syncthreads();

        // ---- S = Q K^T (split bf16, 3 MMAs) ----
        float s[8][4];
#pragma unroll
        for (int n = 0; n < 8; ++n)
#pragma unroll
            for (int j = 0; j < 4; ++j) s[n][j] = 0.f;

#pragma unroll
        for (int ks = 0; ks < 4; ++ks) {
            int ro = (mw + r) * 72 + ks * 16 + cg;
            uint32_t qh0 = *(const uint32_t*)(sQh + ro);
            uint32_t qh1 = *(const uint32_t*)(sQh + ro + 8 * 72);
            uint32_t qh2 = *(const uint32_t*)(sQh + ro + 8);
            uint32_t qh3 = *(const uint32_t*)(sQh + ro + 8 * 72 + 8);
            uint32_t ql0 = *(const uint32_t*)(sQl + ro);
            uint32_t ql1 = *(const uint32_t*)(sQl + ro + 8 * 72);
            uint32_t ql2 = *(const uint32_t*)(sQl + ro + 8);
            uint32_t ql3 = *(const uint32_t*)(sQl + ro + 8 * 72 + 8);
#pragma unroll
            for (int ng = 0; ng < 8; ++ng) {
                int bo = (ng * 8 + r) * 72 + ks * 16 + cg;
                uint32_t kh0 = *(const uint32_t*)(sKh + bo);
                uint32_t kh1 = *(const uint32_t*)(sKh + bo + 8);
                uint32_t kl0 = *(const uint32_t*)(sKl + bo);
                uint32_t kl1 = *(const uint32_t*)(sKl + bo + 8);
                MMA16816(s[ng], qh0, qh1, qh2, qh3, kh0, kh1);
                MMA16816(s[ng], qh0, qh1, qh2, qh3, kl0, kl1);
                MMA16816(s[ng], ql0, ql1, ql2, ql3, kh0, kh1);
            }
        }

        // ---- mask ----
#pragma unroll
        for (int ng = 0; ng < 8; ++ng) {
            float mk0 = smask[ng * 8 + cg];
            float mk1 = smask[ng * 8 + cg + 1];
            if (mk0 == 0.f) { s[ng][0] = -1e30f; s[ng][2] = -1e30f; }
            if (mk1 == 0.f) { s[ng][1] = -1e30f; s[ng][3] = -1e30f; }
        }

        // ---- online softmax on fragments (rows mw+r and mw+r+8) ----
        float rm0 = -1e30f, rm1 = -1e30f;
#pragma unroll
        for (int ng = 0; ng < 8; ++ng) {
            rm0 = fmaxf(rm0, fmaxf(s[ng][0], s[ng][1]));
            rm1 = fmaxf(rm1, fmaxf(s[ng][2], s[ng][3]));
        }
        rm0 = fmaxf(rm0, __shfl_xor_sync(0xffffffffu, rm0, 1));
        rm0 = fmaxf(rm0, __shfl_xor_sync(0xffffffffu, rm0, 2));
        rm1 = fmaxf(rm1, __shfl_xor_sync(0xffffffffu, rm1, 1));
        rm1 = fmaxf(rm1, __shfl_xor_sync(0xffffffffu, rm1, 2));

        float mn0 = fmaxf(m[0], rm0), mn1 = fmaxf(m[1], rm1);
        float sc0 = __expf(m[0] - mn0), sc1 = __expf(m[1] - mn1);
        float rs0 = 0.f, rs1 = 0.f;
#pragma unroll
        for (int ng = 0; ng < 8; ++ng) {
            s[ng][0] = __expf(s[ng][0] - mn0);
            s[ng][1] = __expf(s[ng][1] - mn0);
            s[ng][2] = __expf(s[ng][2] - mn1);
            s[ng][3] = __expf(s[ng][3] - mn1);
            rs0 += s[ng][0] + s[ng][1];
            rs1 += s[ng][2] + s[ng][3];
        }
        rs0 += __shfl_xor_sync(0xffffffffu, rs0, 1);
        rs0 += __shfl_xor_sync(0xffffffffu, rs0, 2);
        rs1 += __shfl_xor_sync(0xffffffffu, rs1, 1);
        rs1 += __shfl_xor_sync(0xffffffffu, rs1, 2);

        l[0] = l[0] * sc0 + rs0;  m[0] = mn0;
        l[1] = l[1] * sc1 + rs1;  m[1] = mn1;
#pragma unroll
        for (int ng = 0; ng < 8; ++ng) {
            o[ng][0] *= sc0; o[ng][1] *= sc0;
            o[ng][2] *= sc1; o[ng][3] *= sc1;
        }

        // ---- O += P V (P from regs, split bf16, 3 MMAs) ----
#pragma unroll
        for (int ks = 0; ks < 4; ++ks) {
            float* sa = s[2 * ks];
            float* sc = s[2 * ks + 1];
            uint32_t ph0 = packbf(sa[0], sa[1]);
            uint32_t ph1 = packbf(sa[2], sa[3]);
            uint32_t ph2 = packbf(sc[0], sc[1]);
            uint32_t ph3 = packbf(sc[2], sc[3]);
            uint32_t pl0 = packbf(bfres(sa[0]), bfres(sa[1]));
            uint32_t pl1 = packbf(bfres(sa[2]), bfres(sa[3]));
            uint32_t pl2 = packbf(bfres(sc[0]), bfres(sc[1]));
            uint32_t pl3 = packbf(bfres(sc[2]), bfres(sc[3]));
#pragma unroll
            for (int ng = 0; ng < 8; ++ng) {
                int bo = (ng * 8 + r) * 72 + ks * 16 + cg;
                uint32_t vh0 = *(const uint32_t*)(sVh + bo);
                uint32_t vh1 = *(const uint32_t*)(sVh + bo + 8);
                uint32_t vl0 = *(const uint32_t*)(sVl + bo);
                uint32_t vl1 = *(const uint32_t*)(sVl + bo + 8);
                MMA16816(o[ng], ph0, ph1, ph2, ph3, vh0, vh1);
                MMA16816(o[ng], ph0, ph1, ph2, ph3, vl0, vl1);
                MMA16816(o[ng], pl0, pl1, pl2, pl3, vh0, vh1);
            }
        }
    }

    // epilogue
    float inv0 = 1.f / l[0], inv1 = 1.f / l[1];
    float* row0 = g_conc + ((size_t)b * LQ + q0 + mw + r) * 512 + hh * 64;
    float* row1 = row0 + 8 * 512;
#pragma unroll
    for (int ng = 0; ng < 8; ++ng) {
        *(float2*)(row0 + ng * 8 + cg) = make_float2(o[ng][0] * inv0, o[ng][1] * inv0);
        *(float2*)(row1 + ng * 8 + cg) = make_float2(o[ng][2] * inv1, o[ng][3] * inv1);
    }
}

// ---------------------------------------------------------------------------
// LayerNorm over last dim (512)
// ---------------------------------------------------------------------------
__global__ __launch_bounds__(128) void ln_kernel(
    const float* __restrict__ gamma, const float* __restrict__ beta,
    float* __restrict__ out)
{
    const int row = blockIdx.x;
    const float* x = g_conc + (size_t)row * 512;
    const int tid = threadIdx.x;

    float v[4];
    float s = 0.f;
#pragma unroll
    for (int i = 0; i < 4; ++i) { v[i] = x[tid + i * 128]; s += v[i]; }

    __shared__ float red1[4];
    __shared__ float red2[4];
#pragma unroll
    for (int off = 16; off >= 1; off >>= 1)
        s += __shfl_xor_sync(0xffffffffu, s, off);
    if ((tid & 31) == 0) red1[tid >> 5] = s;
    __syncthreads();
    float mean = (red1[0] + red1[1] + red1[2] + red1[3]) * (1.f / 512.f);

    float q = 0.f;
#pragma unroll
    for (int i = 0; i < 4; ++i) { float d = v[i] - mean; q += d * d; }
#pragma unroll
    for (int off = 16; off >= 1; off >>= 1)
        q += __shfl_xor_sync(0xffffffffu, q, off);
    if ((tid & 31) == 0) red2[tid >> 5] = q;
    __syncthreads();
    float var  = (red2[0] + red2[1] + red2[2] + red2[3]) * (1.f / 512.f);
    float rstd = rsqrtf(var + 1e-14f);
    float g = gamma[0], be = beta[0];
#pragma unroll
    for (int i = 0; i < 4; ++i)
        out[(size_t)row * 512 + tid + i * 128] = (v[i] - mean) * rstd * g + be;
}

// ---------------------------------------------------------------------------
extern "C" void kernel_launch(void* const* d_in, const int* in_sizes, int n_in,
                              void* d_out, int out_size)
{
    const float* query = (const float*)d_in[0];
    const float* key_t = (const float*)d_in[1];
    const float* value = (const float*)d_in[2];
    const float* mask  = (const float*)d_in[3];
    const float* Wq    = (const float*)d_in[4];
    const float* Wk    = (const float*)d_in[5];
    const float* Wv    = (const float*)d_in[6];
    const float* gamma = (const float*)d_in[7];
    const float* beta  = (const float*)d_in[8];
    float* out = (float*)d_out;

    static int attr_set = 0;
    if (!attr_set) {
        cudaFuncSetAttribute(proj_mma_kernel,
                             cudaFuncAttributeMaxDynamicSharedMemorySize, PROJ_SMEM);
        cudaFuncSetAttribute(attn_mma_kernel,
                             cudaFuncAttributeMaxDynamicSharedMemorySize, ATTN_SMEM);
        attr_set = 1;
    }

    convert_x_kernel<<<dim3(4096, 3), 256>>>(query, key_t, value);
    convert_w_kernel<<<dim3(3, 8), 256>>>(Wq, Wk, Wv);

    proj_mma_kernel<<<dim3(LQ / 128, H, 3 * B), 256, PROJ_SMEM>>>();
    vt_kernel<<<dim3(32, 2, 64), dim3(32, 8)>>>();

    attn_mma_kernel<<<dim3(LQ / 128, B * H), 256, ATTN_SMEM>>>(mask);

    ln_kernel<<<B * LQ, 128>>>(gamma, beta, out);
}